// round 2
// baseline (speedup 1.0000x reference)
#include <cuda_runtime.h>
#include <math.h>

#define B_    128
#define SDEC  256
#define SENC  256
#define IDIM  256
#define HDIM  512
#define ODIM  256
#define G4H   2048
#define MROWS 32768   // B_*SDEC == B_*SENC

// ---------------- scratch (device globals; no allocs allowed) ----------------
__device__ float g_xW[(size_t)MROWS * G4H];   // x@W_ih^T + b_ih + b_hh (256 MB)
__device__ float g_K [(size_t)MROWS * HDIM];  // enc@Wk^T + bk
__device__ float g_V [(size_t)MROWS * HDIM];  // K@Wv^T + bv
__device__ float g_H [(size_t)MROWS * HDIM];  // all h_t
__device__ float g_Q [(size_t)MROWS * HDIM];  // H@Wq^T + bq
__device__ float g_HC[(size_t)MROWS * HDIM];  // h + context
__device__ float g_S [(size_t)B_ * SDEC * SENC]; // attention scores/probs (32 MB)
__device__ float g_hA[B_ * HDIM];
__device__ float g_hB[B_ * HDIM];
__device__ float g_c [B_ * HDIM];
__device__ float g_bsum[G4H];

__device__ __forceinline__ float sigmoidf_(float x) { return 1.0f / (1.0f + __expf(-x)); }

// ---------------- bias sum ----------------
__global__ void bias_sum_kernel(const float* __restrict__ b_ih, const float* __restrict__ b_hh) {
    int i = blockIdx.x * 256 + threadIdx.x;
    if (i < G4H) g_bsum[i] = b_ih[i] + b_hh[i];
}

// ---------------- zero h0 / c0 ----------------
__global__ void zero_state_kernel() {
    int i = blockIdx.x * 256 + threadIdx.x;
    if (i < B_ * HDIM) { g_hA[i] = 0.f; g_c[i] = 0.f; }
}

// ---------------- NT SGEMM: C[m,n] = alpha * sum_k A[m,k]*B[n,k] + bias[n] ----
// 128x128 tile, TK=8, 256 threads, 8x8 microtile. Batched via blockIdx.z strides.
__global__ __launch_bounds__(256) void sgemm_nt(
    const float* __restrict__ A, const float* __restrict__ B,
    const float* __restrict__ bias, float* __restrict__ C,
    int M, int N, int K, float alpha,
    size_t sA, size_t sB, size_t sC)
{
    __shared__ __align__(16) float As[8][128];
    __shared__ __align__(16) float Bs[8][128];

    const int z = blockIdx.z;
    A += (size_t)z * sA; B += (size_t)z * sB; C += (size_t)z * sC;

    const int tid = threadIdx.x;
    const int m0 = blockIdx.y * 128, n0 = blockIdx.x * 128;
    const int lr = tid >> 1;
    const int lc = (tid & 1) * 4;
    const float* Ag = A + (size_t)(m0 + lr) * K + lc;
    const float* Bg = B + (size_t)(n0 + lr) * K + lc;
    const int tx = tid & 15, ty = tid >> 4;

    float acc[8][8];
#pragma unroll
    for (int i = 0; i < 8; i++)
#pragma unroll
        for (int j = 0; j < 8; j++) acc[i][j] = 0.f;

    for (int k0 = 0; k0 < K; k0 += 8) {
        float4 a = *(const float4*)(Ag + k0);
        float4 b = *(const float4*)(Bg + k0);
        __syncthreads();
        As[lc + 0][lr] = a.x; As[lc + 1][lr] = a.y; As[lc + 2][lr] = a.z; As[lc + 3][lr] = a.w;
        Bs[lc + 0][lr] = b.x; Bs[lc + 1][lr] = b.y; Bs[lc + 2][lr] = b.z; Bs[lc + 3][lr] = b.w;
        __syncthreads();
#pragma unroll
        for (int kk = 0; kk < 8; kk++) {
            float av[8], bv[8];
            *(float4*)(av)     = *(const float4*)&As[kk][ty * 8];
            *(float4*)(av + 4) = *(const float4*)&As[kk][ty * 8 + 4];
            *(float4*)(bv)     = *(const float4*)&Bs[kk][tx * 8];
            *(float4*)(bv + 4) = *(const float4*)&Bs[kk][tx * 8 + 4];
#pragma unroll
            for (int i = 0; i < 8; i++)
#pragma unroll
                for (int j = 0; j < 8; j++) acc[i][j] = fmaf(av[i], bv[j], acc[i][j]);
        }
    }

    float bv0[8];
#pragma unroll
    for (int j = 0; j < 8; j++) bv0[j] = bias ? bias[n0 + tx * 8 + j] : 0.f;

#pragma unroll
    for (int i = 0; i < 8; i++) {
        size_t off = (size_t)(m0 + ty * 8 + i) * N + n0 + tx * 8;
        float4 o0, o1;
        o0.x = alpha * acc[i][0] + bv0[0]; o0.y = alpha * acc[i][1] + bv0[1];
        o0.z = alpha * acc[i][2] + bv0[2]; o0.w = alpha * acc[i][3] + bv0[3];
        o1.x = alpha * acc[i][4] + bv0[4]; o1.y = alpha * acc[i][5] + bv0[5];
        o1.z = alpha * acc[i][6] + bv0[6]; o1.w = alpha * acc[i][7] + bv0[7];
        *(float4*)(C + off)     = o0;
        *(float4*)(C + off + 4) = o1;
    }
}

// ---------------- NN SGEMM + elementwise add: C = A*B + E (batched) ----------
__global__ __launch_bounds__(256) void sgemm_nn_addE(
    const float* __restrict__ A, const float* __restrict__ B,
    const float* __restrict__ E, float* __restrict__ C,
    int M, int N, int K,
    size_t sA, size_t sB, size_t sE, size_t sC)
{
    __shared__ __align__(16) float As[8][128];
    __shared__ __align__(16) float Bs[8][128];

    const int z = blockIdx.z;
    A += (size_t)z * sA; B += (size_t)z * sB; E += (size_t)z * sE; C += (size_t)z * sC;

    const int tid = threadIdx.x;
    const int m0 = blockIdx.y * 128, n0 = blockIdx.x * 128;
    const int lr = tid >> 1;
    const int lc = (tid & 1) * 4;
    const float* Ag = A + (size_t)(m0 + lr) * K + lc;
    const int lrB = tid >> 5;              // 0..7
    const int lcB = (tid & 31) * 4;        // 0..124
    const int tx = tid & 15, ty = tid >> 4;

    float acc[8][8];
#pragma unroll
    for (int i = 0; i < 8; i++)
#pragma unroll
        for (int j = 0; j < 8; j++) acc[i][j] = 0.f;

    for (int k0 = 0; k0 < K; k0 += 8) {
        float4 a = *(const float4*)(Ag + k0);
        float4 b = *(const float4*)(B + (size_t)(k0 + lrB) * N + n0 + lcB);
        __syncthreads();
        As[lc + 0][lr] = a.x; As[lc + 1][lr] = a.y; As[lc + 2][lr] = a.z; As[lc + 3][lr] = a.w;
        *(float4*)&Bs[lrB][lcB] = b;
        __syncthreads();
#pragma unroll
        for (int kk = 0; kk < 8; kk++) {
            float av[8], bv[8];
            *(float4*)(av)     = *(const float4*)&As[kk][ty * 8];
            *(float4*)(av + 4) = *(const float4*)&As[kk][ty * 8 + 4];
            *(float4*)(bv)     = *(const float4*)&Bs[kk][tx * 8];
            *(float4*)(bv + 4) = *(const float4*)&Bs[kk][tx * 8 + 4];
#pragma unroll
            for (int i = 0; i < 8; i++)
#pragma unroll
                for (int j = 0; j < 8; j++) acc[i][j] = fmaf(av[i], bv[j], acc[i][j]);
        }
    }

#pragma unroll
    for (int i = 0; i < 8; i++) {
        size_t off = (size_t)(m0 + ty * 8 + i) * N + n0 + tx * 8;
        float4 e0 = *(const float4*)(E + off);
        float4 e1 = *(const float4*)(E + off + 4);
        float4 o0, o1;
        o0.x = acc[i][0] + e0.x; o0.y = acc[i][1] + e0.y;
        o0.z = acc[i][2] + e0.z; o0.w = acc[i][3] + e0.w;
        o1.x = acc[i][4] + e1.x; o1.y = acc[i][5] + e1.y;
        o1.z = acc[i][6] + e1.z; o1.w = acc[i][7] + e1.w;
        *(float4*)(C + off)     = o0;
        *(float4*)(C + off + 4) = o1;
    }
}

// ---------------- LSTM step: gates = xW[:,t,:] + h_prev @ W_hh^T; cell update -
// Block = u-tile of 4 hidden units (16 gate rows), all 128 batch rows. 128 blocks.
__global__ __launch_bounds__(256) void lstm_step(
    const float* __restrict__ W_hh,
    const float* __restrict__ hprev, float* __restrict__ hcur, int t)
{
    __shared__ float ws[16 * 512];     // [k][r], 32 KB
    __shared__ float pool[16 * 136];   // hs[kk][b] during GEMM; gsm[r][b] after

    const int tid = threadIdx.x;
    const int u0 = blockIdx.x * 4;

    // Load the 16 W_hh rows this block needs: row(r) = (r>>2)*HDIM + u0 + (r&3)
    for (int idx = tid; idx < 16 * 512; idx += 256) {
        int r = idx >> 9, k = idx & 511;
        int rowg = ((r >> 2) * HDIM) + u0 + (r & 3);
        ws[k * 16 + r] = W_hh[(size_t)rowg * HDIM + k];
    }

    const int tx = tid & 15, ty = tid >> 4;   // tx = gate-row r, ty = b-group
    const int hb = tid >> 1, hc = (tid & 1) * 8;

    float acc[8];
#pragma unroll
    for (int i = 0; i < 8; i++) acc[i] = 0.f;

    for (int k0 = 0; k0 < HDIM; k0 += 16) {
        float4 x0 = *(const float4*)(hprev + (size_t)hb * HDIM + k0 + hc);
        float4 x1 = *(const float4*)(hprev + (size_t)hb * HDIM + k0 + hc + 4);
        __syncthreads();
        pool[(hc + 0) * 136 + hb] = x0.x; pool[(hc + 1) * 136 + hb] = x0.y;
        pool[(hc + 2) * 136 + hb] = x0.z; pool[(hc + 3) * 136 + hb] = x0.w;
        pool[(hc + 4) * 136 + hb] = x1.x; pool[(hc + 5) * 136 + hb] = x1.y;
        pool[(hc + 6) * 136 + hb] = x1.z; pool[(hc + 7) * 136 + hb] = x1.w;
        __syncthreads();
#pragma unroll
        for (int kk = 0; kk < 16; kk++) {
            float w = ws[(k0 + kk) * 16 + tx];
            float hv[8];
            *(float4*)(hv)     = *(const float4*)&pool[kk * 136 + ty * 8];
            *(float4*)(hv + 4) = *(const float4*)&pool[kk * 136 + ty * 8 + 4];
#pragma unroll
            for (int i = 0; i < 8; i++) acc[i] = fmaf(hv[i], w, acc[i]);
        }
    }
    __syncthreads();   // done reading hs; pool becomes gsm

    // add precomputed x-part (+biases) and stage gates into smem
    {
        int g = tx >> 2, iu = tx & 3;
        int col = g * HDIM + u0 + iu;
#pragma unroll
        for (int i = 0; i < 8; i++) {
            int b = ty * 8 + i;
            float gv = acc[i] + g_xW[((size_t)b * SDEC + t) * G4H + col];
            pool[tx * 128 + b] = gv;
        }
    }
    __syncthreads();

    // cell + hidden update: 4 u x 128 b = 512 items
    for (int it = tid; it < 512; it += 256) {
        int u = it >> 7, b = it & 127;
        float ig = sigmoidf_(pool[(0 * 4 + u) * 128 + b]);
        float fg = sigmoidf_(pool[(1 * 4 + u) * 128 + b]);
        float gg = tanhf   (pool[(2 * 4 + u) * 128 + b]);
        float og = sigmoidf_(pool[(3 * 4 + u) * 128 + b]);
        int ci = b * HDIM + u0 + u;
        float c = fg * g_c[ci] + ig * gg;
        g_c[ci] = c;
        float h = og * tanhf(c);
        hcur[ci] = h;
        g_H[((size_t)b * SDEC + t) * HDIM + u0 + u] = h;
    }
}

// ---------------- softmax over last dim (256) ----------------
__global__ __launch_bounds__(256) void softmax256(float* __restrict__ S) {
    __shared__ float red[256];
    const int t = threadIdx.x;
    float* p = S + (size_t)blockIdx.x * SENC;
    float v = p[t];
    red[t] = v; __syncthreads();
    for (int s = 128; s > 0; s >>= 1) { if (t < s) red[t] = fmaxf(red[t], red[t + s]); __syncthreads(); }
    float mx = red[0]; __syncthreads();
    float e = __expf(v - mx);
    red[t] = e; __syncthreads();
    for (int s = 128; s > 0; s >>= 1) { if (t < s) red[t] += red[t + s]; __syncthreads(); }
    p[t] = e * (1.0f / red[0]);
}

// ---------------- host ----------------
extern "C" void kernel_launch(void* const* d_in, const int* in_sizes, int n_in,
                              void* d_out, int out_size) {
    const float* x    = (const float*)d_in[0];
    const float* enc  = (const float*)d_in[1];
    const float* W_ih = (const float*)d_in[2];
    const float* W_hh = (const float*)d_in[3];
    const float* b_ih = (const float*)d_in[4];
    const float* b_hh = (const float*)d_in[5];
    const float* Wq   = (const float*)d_in[6];
    const float* bq   = (const float*)d_in[7];
    const float* Wk   = (const float*)d_in[8];
    const float* bk   = (const float*)d_in[9];
    const float* Wv   = (const float*)d_in[10];
    const float* bv   = (const float*)d_in[11];
    const float* Wfc  = (const float*)d_in[12];
    const float* bfc  = (const float*)d_in[13];
    float* out = (float*)d_out;

    float *p_xW, *p_K, *p_V, *p_H, *p_Q, *p_HC, *p_S, *p_hA, *p_hB, *p_bsum;
    cudaGetSymbolAddress((void**)&p_xW,  g_xW);
    cudaGetSymbolAddress((void**)&p_K,   g_K);
    cudaGetSymbolAddress((void**)&p_V,   g_V);
    cudaGetSymbolAddress((void**)&p_H,   g_H);
    cudaGetSymbolAddress((void**)&p_Q,   g_Q);
    cudaGetSymbolAddress((void**)&p_HC,  g_HC);
    cudaGetSymbolAddress((void**)&p_S,   g_S);
    cudaGetSymbolAddress((void**)&p_hA,  g_hA);
    cudaGetSymbolAddress((void**)&p_hB,  g_hB);
    cudaGetSymbolAddress((void**)&p_bsum,g_bsum);

    const float scale = 1.0f / sqrtf((float)HDIM);

    // combined bias, zero h0/c0
    bias_sum_kernel<<<G4H / 256, 256>>>(b_ih, b_hh);
    zero_state_kernel<<<(B_ * HDIM) / 256, 256>>>();

    // xW = x @ W_ih^T + (b_ih + b_hh)      [32768 x 2048], K=256
    sgemm_nt<<<dim3(G4H / 128, MROWS / 128, 1), 256>>>(
        x, W_ih, p_bsum, p_xW, MROWS, G4H, IDIM, 1.0f, 0, 0, 0);
    // K = enc @ Wk^T + bk                  [32768 x 512], K=512
    sgemm_nt<<<dim3(HDIM / 128, MROWS / 128, 1), 256>>>(
        enc, Wk, bk, p_K, MROWS, HDIM, HDIM, 1.0f, 0, 0, 0);
    // V = K @ Wv^T + bv
    sgemm_nt<<<dim3(HDIM / 128, MROWS / 128, 1), 256>>>(
        p_K, Wv, bv, p_V, MROWS, HDIM, HDIM, 1.0f, 0, 0, 0);

    // sequential LSTM
    for (int t = 0; t < SDEC; t++) {
        const float* hp = (t & 1) ? p_hB : p_hA;
        float*       hcv = (t & 1) ? p_hA : p_hB;
        lstm_step<<<HDIM / 4, 256>>>(W_hh, hp, hcv, t);
    }

    // Q = H @ Wq^T + bq
    sgemm_nt<<<dim3(HDIM / 128, MROWS / 128, 1), 256>>>(
        p_H, Wq, bq, p_Q, MROWS, HDIM, HDIM, 1.0f, 0, 0, 0);

    // scores: per-batch S[t,s] = scale * Q[t,:]·K[s,:]
    sgemm_nt<<<dim3(SENC / 128, SDEC / 128, B_), 256>>>(
        p_Q, p_K, nullptr, p_S, SDEC, SENC, HDIM, scale,
        (size_t)SDEC * HDIM, (size_t)SENC * HDIM, (size_t)SDEC * SENC);

    softmax256<<<B_ * SDEC, 256>>>(p_S);

    // context + h: HC[t,h] = sum_s S[t,s] * V[s,h] + H[t,h]
    sgemm_nn_addE<<<dim3(HDIM / 128, SDEC / 128, B_), 256>>>(
        p_S, p_V, p_H, p_HC, SDEC, HDIM, SENC,
        (size_t)SDEC * SENC, (size_t)SENC * HDIM,
        (size_t)SDEC * HDIM, (size_t)SDEC * HDIM);

    // out = HC @ Wfc^T + bfc               [32768 x 256]
    sgemm_nt<<<dim3(ODIM / 128, MROWS / 128, 1), 256>>>(
        p_HC, Wfc, bfc, out, MROWS, ODIM, HDIM, 1.0f, 0, 0, 0);
}

// round 3
// speedup vs baseline: 1.0583x; 1.0583x over previous
#include <cuda_runtime.h>
#include <math.h>

#define B_    128
#define SDEC  256
#define SENC  256
#define IDIM  256
#define HDIM  512
#define ODIM  256
#define G4H   2048
#define MROWS 32768   // B_*SDEC == B_*SENC
#define NBLK  128     // persistent LSTM blocks (<=148, all co-resident)

// ---------------- scratch (device globals; no allocs allowed) ----------------
__device__ float g_xW[(size_t)MROWS * G4H];   // x@W_ih^T + b_ih + b_hh (256 MB)
__device__ float g_K [(size_t)MROWS * HDIM];  // enc@Wk^T + bk
__device__ float g_V [(size_t)MROWS * HDIM];  // K@Wv^T + bv
__device__ float g_H [(size_t)MROWS * HDIM];  // all h_t
__device__ float g_Q [(size_t)MROWS * HDIM];  // H@Wq^T + bq
__device__ float g_HC[(size_t)MROWS * HDIM];  // h + context
__device__ float g_S [(size_t)B_ * SDEC * SENC]; // attention probs (32 MB)
__device__ float g_h2[2][B_ * HDIM];          // h ping-pong
__device__ float g_c [B_ * HDIM];
__device__ float g_bsum[G4H];
__device__ unsigned g_bar_count;
__device__ unsigned g_bar_gen;

__device__ __forceinline__ float sigmoidf_(float x) { return 1.0f / (1.0f + __expf(-x)); }

__device__ __forceinline__ unsigned long long ffma2(unsigned long long a,
                                                    unsigned long long b,
                                                    unsigned long long c) {
    unsigned long long d;
    asm("fma.rn.f32x2 %0, %1, %2, %3;" : "=l"(d) : "l"(a), "l"(b), "l"(c));
    return d;
}
__device__ __forceinline__ unsigned long long dup2(float w) {
    unsigned wu = __float_as_uint(w);
    unsigned long long w2;
    asm("mov.b64 %0, {%1, %1};" : "=l"(w2) : "r"(wu));
    return w2;
}
__device__ __forceinline__ float lo32(unsigned long long v) { return __uint_as_float((unsigned)v); }
__device__ __forceinline__ float hi32(unsigned long long v) { return __uint_as_float((unsigned)(v >> 32)); }

// ---------------- bias sum ----------------
__global__ void bias_sum_kernel(const float* __restrict__ b_ih, const float* __restrict__ b_hh) {
    int i = blockIdx.x * 256 + threadIdx.x;
    if (i < G4H) g_bsum[i] = b_ih[i] + b_hh[i];
}

// ---------------- NT SGEMM: C[m,n] = alpha * sum_k A[m,k]*B[n,k] + bias[n] ----
__global__ __launch_bounds__(256) void sgemm_nt(
    const float* __restrict__ A, const float* __restrict__ B,
    const float* __restrict__ bias, float* __restrict__ C,
    int M, int N, int K, float alpha,
    size_t sA, size_t sB, size_t sC)
{
    __shared__ __align__(16) float As[8][128];
    __shared__ __align__(16) float Bs[8][128];

    const int z = blockIdx.z;
    A += (size_t)z * sA; B += (size_t)z * sB; C += (size_t)z * sC;

    const int tid = threadIdx.x;
    const int m0 = blockIdx.y * 128, n0 = blockIdx.x * 128;
    const int lr = tid >> 1;
    const int lc = (tid & 1) * 4;
    const float* Ag = A + (size_t)(m0 + lr) * K + lc;
    const float* Bg = B + (size_t)(n0 + lr) * K + lc;
    const int tx = tid & 15, ty = tid >> 4;

    float acc[8][8];
#pragma unroll
    for (int i = 0; i < 8; i++)
#pragma unroll
        for (int j = 0; j < 8; j++) acc[i][j] = 0.f;

    for (int k0 = 0; k0 < K; k0 += 8) {
        float4 a = *(const float4*)(Ag + k0);
        float4 b = *(const float4*)(Bg + k0);
        __syncthreads();
        As[lc + 0][lr] = a.x; As[lc + 1][lr] = a.y; As[lc + 2][lr] = a.z; As[lc + 3][lr] = a.w;
        Bs[lc + 0][lr] = b.x; Bs[lc + 1][lr] = b.y; Bs[lc + 2][lr] = b.z; Bs[lc + 3][lr] = b.w;
        __syncthreads();
#pragma unroll
        for (int kk = 0; kk < 8; kk++) {
            float av[8], bv[8];
            *(float4*)(av)     = *(const float4*)&As[kk][ty * 8];
            *(float4*)(av + 4) = *(const float4*)&As[kk][ty * 8 + 4];
            *(float4*)(bv)     = *(const float4*)&Bs[kk][tx * 8];
            *(float4*)(bv + 4) = *(const float4*)&Bs[kk][tx * 8 + 4];
#pragma unroll
            for (int i = 0; i < 8; i++)
#pragma unroll
                for (int j = 0; j < 8; j++) acc[i][j] = fmaf(av[i], bv[j], acc[i][j]);
        }
    }

    float bv0[8];
#pragma unroll
    for (int j = 0; j < 8; j++) bv0[j] = bias ? bias[n0 + tx * 8 + j] : 0.f;

#pragma unroll
    for (int i = 0; i < 8; i++) {
        size_t off = (size_t)(m0 + ty * 8 + i) * N + n0 + tx * 8;
        float4 o0, o1;
        o0.x = alpha * acc[i][0] + bv0[0]; o0.y = alpha * acc[i][1] + bv0[1];
        o0.z = alpha * acc[i][2] + bv0[2]; o0.w = alpha * acc[i][3] + bv0[3];
        o1.x = alpha * acc[i][4] + bv0[4]; o1.y = alpha * acc[i][5] + bv0[5];
        o1.z = alpha * acc[i][6] + bv0[6]; o1.w = alpha * acc[i][7] + bv0[7];
        *(float4*)(C + off)     = o0;
        *(float4*)(C + off + 4) = o1;
    }
}

// ---------------- NN SGEMM + elementwise add: C = A*B + E (batched) ----------
__global__ __launch_bounds__(256) void sgemm_nn_addE(
    const float* __restrict__ A, const float* __restrict__ B,
    const float* __restrict__ E, float* __restrict__ C,
    int M, int N, int K,
    size_t sA, size_t sB, size_t sE, size_t sC)
{
    __shared__ __align__(16) float As[8][128];
    __shared__ __align__(16) float Bs[8][128];

    const int z = blockIdx.z;
    A += (size_t)z * sA; B += (size_t)z * sB; E += (size_t)z * sE; C += (size_t)z * sC;

    const int tid = threadIdx.x;
    const int m0 = blockIdx.y * 128, n0 = blockIdx.x * 128;
    const int lr = tid >> 1;
    const int lc = (tid & 1) * 4;
    const float* Ag = A + (size_t)(m0 + lr) * K + lc;
    const int lrB = tid >> 5;
    const int lcB = (tid & 31) * 4;
    const int tx = tid & 15, ty = tid >> 4;

    float acc[8][8];
#pragma unroll
    for (int i = 0; i < 8; i++)
#pragma unroll
        for (int j = 0; j < 8; j++) acc[i][j] = 0.f;

    for (int k0 = 0; k0 < K; k0 += 8) {
        float4 a = *(const float4*)(Ag + k0);
        float4 b = *(const float4*)(B + (size_t)(k0 + lrB) * N + n0 + lcB);
        __syncthreads();
        As[lc + 0][lr] = a.x; As[lc + 1][lr] = a.y; As[lc + 2][lr] = a.z; As[lc + 3][lr] = a.w;
        *(float4*)&Bs[lrB][lcB] = b;
        __syncthreads();
#pragma unroll
        for (int kk = 0; kk < 8; kk++) {
            float av[8], bv[8];
            *(float4*)(av)     = *(const float4*)&As[kk][ty * 8];
            *(float4*)(av + 4) = *(const float4*)&As[kk][ty * 8 + 4];
            *(float4*)(bv)     = *(const float4*)&Bs[kk][tx * 8];
            *(float4*)(bv + 4) = *(const float4*)&Bs[kk][tx * 8 + 4];
#pragma unroll
            for (int i = 0; i < 8; i++)
#pragma unroll
                for (int j = 0; j < 8; j++) acc[i][j] = fmaf(av[i], bv[j], acc[i][j]);
        }
    }

#pragma unroll
    for (int i = 0; i < 8; i++) {
        size_t off = (size_t)(m0 + ty * 8 + i) * N + n0 + tx * 8;
        float4 e0 = *(const float4*)(E + off);
        float4 e1 = *(const float4*)(E + off + 4);
        float4 o0, o1;
        o0.x = acc[i][0] + e0.x; o0.y = acc[i][1] + e0.y;
        o0.z = acc[i][2] + e0.z; o0.w = acc[i][3] + e0.w;
        o1.x = acc[i][4] + e1.x; o1.y = acc[i][5] + e1.y;
        o1.z = acc[i][6] + e1.z; o1.w = acc[i][7] + e1.w;
        *(float4*)(C + off)     = o0;
        *(float4*)(C + off + 4) = o1;
    }
}

// ---------------- persistent LSTM recurrence ----------------
// 128 blocks x 256 threads, all co-resident. Block owns 4 hidden units
// (16 gate rows). W_hh slice staged in smem ONCE. One grid barrier per step.
__global__ __launch_bounds__(256) void lstm_persistent(const float* __restrict__ W_hh)
{
    __shared__ float ws[16 * 512];     // [k][r] 32 KB, loaded once
    __shared__ float pool[16 * 136];   // h tile [kk][b] during GEMM; gates [r][b] after

    const int tid = threadIdx.x;
    const int u0 = blockIdx.x * 4;
    const int tx = tid & 15, ty = tid >> 4;   // tx = gate-row r, ty = batch-group
    const int hb = tid >> 1, hc = (tid & 1) * 8;

    // one-time: load W_hh slice into smem
    for (int idx = tid; idx < 16 * 512; idx += 256) {
        int r = idx >> 9, k = idx & 511;
        int rowg = ((r >> 2) * HDIM) + u0 + (r & 3);
        ws[k * 16 + r] = W_hh[(size_t)rowg * HDIM + k];
    }

    // one-time: zero h0, c0 (block's slice of batch rows for h; own units for c)
    {
        float* h0 = g_h2[0];
        for (int i = tid + blockIdx.x * 256; i < B_ * HDIM; i += NBLK * 256) h0[i] = 0.f;
        for (int b = tid; b < B_; b += 256)
#pragma unroll
            for (int u = 0; u < 4; u++) g_c[b * HDIM + u0 + u] = 0.f;
    }

    // grid barrier helper state
    unsigned* cnt = &g_bar_count;
    volatile unsigned* gen = &g_bar_gen;

    // initial barrier: h0/c0 visible everywhere
    __syncthreads();
    if (tid == 0) {
        unsigned g = *gen;
        __threadfence();
        if (atomicAdd(cnt, 1) == NBLK - 1) {
            *cnt = 0;
            __threadfence();
            atomicExch((unsigned*)gen, g + 1);
        } else {
            while (*gen == g) __nanosleep(32);
        }
    }
    __syncthreads();

    const int gsel = tx >> 2, iu = tx & 3;
    const int xcol = gsel * HDIM + u0 + iu;

    for (int t = 0; t < SDEC; t++) {
        const float* __restrict__ hprev = g_h2[t & 1];
        float* __restrict__ hcur = g_h2[(t + 1) & 1];

        // prefetch x-part of gates for this (tx,ty) tile
        float xg[8];
#pragma unroll
        for (int i = 0; i < 8; i++) {
            int b = ty * 8 + i;
            xg[i] = __ldg(&g_xW[((size_t)b * SDEC + t) * G4H + xcol]);
        }

        unsigned long long acc0 = 0, acc1 = 0, acc2 = 0, acc3 = 0;

        for (int k0 = 0; k0 < HDIM; k0 += 16) {
            float4 x0 = *(const float4*)(hprev + (size_t)hb * HDIM + k0 + hc);
            float4 x1 = *(const float4*)(hprev + (size_t)hb * HDIM + k0 + hc + 4);
            __syncthreads();
            pool[(hc + 0) * 136 + hb] = x0.x; pool[(hc + 1) * 136 + hb] = x0.y;
            pool[(hc + 2) * 136 + hb] = x0.z; pool[(hc + 3) * 136 + hb] = x0.w;
            pool[(hc + 4) * 136 + hb] = x1.x; pool[(hc + 5) * 136 + hb] = x1.y;
            pool[(hc + 6) * 136 + hb] = x1.z; pool[(hc + 7) * 136 + hb] = x1.w;
            __syncthreads();
#pragma unroll
            for (int kk = 0; kk < 16; kk++) {
                unsigned long long w2 = dup2(ws[(k0 + kk) * 16 + tx]);
                const float* pr = &pool[kk * 136 + ty * 8];
                ulonglong2 h01 = *(const ulonglong2*)pr;
                ulonglong2 h23 = *(const ulonglong2*)(pr + 4);
                acc0 = ffma2(h01.x, w2, acc0);
                acc1 = ffma2(h01.y, w2, acc1);
                acc2 = ffma2(h23.x, w2, acc2);
                acc3 = ffma2(h23.y, w2, acc3);
            }
        }
        __syncthreads();   // done reading h tiles; pool becomes gate staging

        // gates = h-part + x-part (+biases, already folded into xW)
        {
            float gv[8];
            gv[0] = lo32(acc0); gv[1] = hi32(acc0);
            gv[2] = lo32(acc1); gv[3] = hi32(acc1);
            gv[4] = lo32(acc2); gv[5] = hi32(acc2);
            gv[6] = lo32(acc3); gv[7] = hi32(acc3);
#pragma unroll
            for (int i = 0; i < 8; i++)
                pool[tx * 128 + ty * 8 + i] = gv[i] + xg[i];
        }
        __syncthreads();

        // cell + hidden update: 4 u x 128 b = 512 items
        for (int it = tid; it < 512; it += 256) {
            int u = it >> 7, b = it & 127;
            float ig = sigmoidf_(pool[(0 * 4 + u) * 128 + b]);
            float fg = sigmoidf_(pool[(1 * 4 + u) * 128 + b]);
            float gg = tanhf   (pool[(2 * 4 + u) * 128 + b]);
            float og = sigmoidf_(pool[(3 * 4 + u) * 128 + b]);
            int ci = b * HDIM + u0 + u;
            float c = fg * g_c[ci] + ig * gg;
            g_c[ci] = c;
            float h = og * tanhf(c);
            hcur[ci] = h;
            g_H[((size_t)b * SDEC + t) * HDIM + u0 + u] = h;
        }

        // grid barrier: publish h_t before anyone starts step t+1
        __syncthreads();
        if (tid == 0) {
            unsigned g = *gen;
            __threadfence();
            if (atomicAdd(cnt, 1) == NBLK - 1) {
                *cnt = 0;
                __threadfence();
                atomicExch((unsigned*)gen, g + 1);
            } else {
                while (*gen == g) __nanosleep(32);
            }
        }
        __syncthreads();
    }
}

// ---------------- softmax over last dim (256) ----------------
__global__ __launch_bounds__(256) void softmax256(float* __restrict__ S) {
    __shared__ float red[256];
    const int t = threadIdx.x;
    float* p = S + (size_t)blockIdx.x * SENC;
    float v = p[t];
    red[t] = v; __syncthreads();
    for (int s = 128; s > 0; s >>= 1) { if (t < s) red[t] = fmaxf(red[t], red[t + s]); __syncthreads(); }
    float mx = red[0]; __syncthreads();
    float e = __expf(v - mx);
    red[t] = e; __syncthreads();
    for (int s = 128; s > 0; s >>= 1) { if (t < s) red[t] += red[t + s]; __syncthreads(); }
    p[t] = e * (1.0f / red[0]);
}

// ---------------- host ----------------
extern "C" void kernel_launch(void* const* d_in, const int* in_sizes, int n_in,
                              void* d_out, int out_size) {
    const float* x    = (const float*)d_in[0];
    const float* enc  = (const float*)d_in[1];
    const float* W_ih = (const float*)d_in[2];
    const float* W_hh = (const float*)d_in[3];
    const float* b_ih = (const float*)d_in[4];
    const float* b_hh = (const float*)d_in[5];
    const float* Wq   = (const float*)d_in[6];
    const float* bq   = (const float*)d_in[7];
    const float* Wk   = (const float*)d_in[8];
    const float* bk   = (const float*)d_in[9];
    const float* Wv   = (const float*)d_in[10];
    const float* bv   = (const float*)d_in[11];
    const float* Wfc  = (const float*)d_in[12];
    const float* bfc  = (const float*)d_in[13];
    float* out = (float*)d_out;

    float *p_xW, *p_K, *p_V, *p_H, *p_Q, *p_HC, *p_S, *p_bsum;
    cudaGetSymbolAddress((void**)&p_xW,  g_xW);
    cudaGetSymbolAddress((void**)&p_K,   g_K);
    cudaGetSymbolAddress((void**)&p_V,   g_V);
    cudaGetSymbolAddress((void**)&p_H,   g_H);
    cudaGetSymbolAddress((void**)&p_Q,   g_Q);
    cudaGetSymbolAddress((void**)&p_HC,  g_HC);
    cudaGetSymbolAddress((void**)&p_S,   g_S);
    cudaGetSymbolAddress((void**)&p_bsum,g_bsum);

    const float scale = 1.0f / sqrtf((float)HDIM);

    bias_sum_kernel<<<G4H / 256, 256>>>(b_ih, b_hh);

    // xW = x @ W_ih^T + (b_ih + b_hh)      [32768 x 2048], K=256
    sgemm_nt<<<dim3(G4H / 128, MROWS / 128, 1), 256>>>(
        x, W_ih, p_bsum, p_xW, MROWS, G4H, IDIM, 1.0f, 0, 0, 0);
    // K = enc @ Wk^T + bk
    sgemm_nt<<<dim3(HDIM / 128, MROWS / 128, 1), 256>>>(
        enc, Wk, bk, p_K, MROWS, HDIM, HDIM, 1.0f, 0, 0, 0);
    // V = K @ Wv^T + bv
    sgemm_nt<<<dim3(HDIM / 128, MROWS / 128, 1), 256>>>(
        p_K, Wv, bv, p_V, MROWS, HDIM, HDIM, 1.0f, 0, 0, 0);

    // entire sequential LSTM in one persistent launch
    lstm_persistent<<<NBLK, 256>>>(W_hh);

    // Q = H @ Wq^T + bq
    sgemm_nt<<<dim3(HDIM / 128, MROWS / 128, 1), 256>>>(
        p_H, Wq, bq, p_Q, MROWS, HDIM, HDIM, 1.0f, 0, 0, 0);

    // scores: per-batch S[t,s] = scale * Q[t,:]·K[s,:]
    sgemm_nt<<<dim3(SENC / 128, SDEC / 128, B_), 256>>>(
        p_Q, p_K, nullptr, p_S, SDEC, SENC, HDIM, scale,
        (size_t)SDEC * HDIM, (size_t)SENC * HDIM, (size_t)SDEC * SENC);

    softmax256<<<B_ * SDEC, 256>>>(p_S);

    // context + h: HC[t,h] = sum_s S[t,s] * V[s,h] + H[t,h]
    sgemm_nn_addE<<<dim3(HDIM / 128, SDEC / 128, B_), 256>>>(
        p_S, p_V, p_H, p_HC, SDEC, HDIM, SENC,
        (size_t)SDEC * SENC, (size_t)SENC * HDIM,
        (size_t)SDEC * HDIM, (size_t)SDEC * HDIM);

    // out = HC @ Wfc^T + bfc               [32768 x 256]
    sgemm_nt<<<dim3(ODIM / 128, MROWS / 128, 1), 256>>>(
        p_HC, Wfc, bfc, out, MROWS, ODIM, HDIM, 1.0f, 0, 0, 0);
}

// round 4
// speedup vs baseline: 1.6759x; 1.5836x over previous
#include <cuda_runtime.h>
#include <math.h>

#define B_    128
#define SDEC  256
#define SENC  256
#define IDIM  256
#define HDIM  512
#define ODIM  256
#define G4H   2048
#define MROWS 32768   // B_*SDEC == B_*SENC

// ---------------- scratch (device globals; no allocs allowed) ----------------
__device__ float g_xW [(size_t)MROWS * G4H];  // x@W_ih^T + b_ih + b_hh  [b*256+t][col]
__device__ float g_xWt[(size_t)MROWS * G4H];  // transposed: [t][col][b]
__device__ float g_K [(size_t)MROWS * HDIM];  // enc@Wk^T + bk
__device__ float g_V [(size_t)MROWS * HDIM];  // K@Wv^T + bv
__device__ float g_H [(size_t)MROWS * HDIM];  // all h_t  [b*256+t][u]
__device__ float g_Q [(size_t)MROWS * HDIM];  // H@Wq^T + bq
__device__ float g_HC[(size_t)MROWS * HDIM];  // h + context
__device__ float g_S [(size_t)B_ * SDEC * SENC]; // attention probs (32 MB)
__device__ float g_h2[2 * 4 * HDIM * 32];     // h ping-pong  [pp][bg][u][32 b]
__device__ float g_bsum[G4H];
__device__ unsigned g_barc[4];
__device__ unsigned g_barg[4];

__device__ __forceinline__ float sigmoidf_(float x) { return 1.0f / (1.0f + __expf(-x)); }

__device__ __forceinline__ unsigned long long ffma2(unsigned long long a,
                                                    unsigned long long b,
                                                    unsigned long long c) {
    unsigned long long d;
    asm("fma.rn.f32x2 %0, %1, %2, %3;" : "=l"(d) : "l"(a), "l"(b), "l"(c));
    return d;
}
__device__ __forceinline__ unsigned long long dup2(float w) {
    unsigned wu = __float_as_uint(w);
    unsigned long long w2;
    asm("mov.b64 %0, {%1, %1};" : "=l"(w2) : "r"(wu));
    return w2;
}
__device__ __forceinline__ float lo32(unsigned long long v) { return __uint_as_float((unsigned)v); }
__device__ __forceinline__ float hi32(unsigned long long v) { return __uint_as_float((unsigned)(v >> 32)); }

// barrier among the 32 blocks of one bg group (pure spin, no nanosleep)
__device__ __forceinline__ void bar_bg(int bg, int tid) {
    if (tid == 0) {
        __threadfence();
        volatile unsigned* genp = &g_barg[bg];
        unsigned g = *genp;
        if (atomicAdd(&g_barc[bg], 1) == 31) {
            g_barc[bg] = 0;
            __threadfence();
            atomicExch((unsigned*)&g_barg[bg], g + 1);
        } else {
            while (*genp == g) { }
        }
        __threadfence();
    }
    __syncthreads();
}

// ---------------- bias sum ----------------
__global__ void bias_sum_kernel(const float* __restrict__ b_ih, const float* __restrict__ b_hh) {
    int i = blockIdx.x * 256 + threadIdx.x;
    if (i < G4H) g_bsum[i] = b_ih[i] + b_hh[i];
}

// ---------------- xW transpose: [b*256+t][col] -> [t][col][b] ----------------
__global__ __launch_bounds__(256) void xw_transpose() {
    __shared__ float tile[32][129];
    const int t  = blockIdx.y;
    const int c0 = blockIdx.x * 32;
    const int tid = threadIdx.x;
    const int rc = tid & 31, rb = tid >> 5;     // read: 32 cols x 8 b per pass
#pragma unroll
    for (int p = 0; p < 16; p++) {
        int b = rb + p * 8;
        tile[rc][b] = g_xW[((size_t)b * SDEC + t) * G4H + c0 + rc];
    }
    __syncthreads();
    const int wb = tid & 127, wc = tid >> 7;    // write: 2 cols x 128 b per pass
#pragma unroll
    for (int p = 0; p < 16; p++) {
        int c = wc + p * 2;
        g_xWt[((size_t)t * G4H + c0 + c) * B_ + wb] = tile[c][wb];
    }
}

// ---------------- NT SGEMM: C[m,n] = alpha * sum_k A[m,k]*B[n,k] + bias[n] ----
__global__ __launch_bounds__(256) void sgemm_nt(
    const float* __restrict__ A, const float* __restrict__ B,
    const float* __restrict__ bias, float* __restrict__ C,
    int M, int N, int K, float alpha,
    size_t sA, size_t sB, size_t sC)
{
    __shared__ __align__(16) float As[8][128];
    __shared__ __align__(16) float Bs[8][128];

    const int z = blockIdx.z;
    A += (size_t)z * sA; B += (size_t)z * sB; C += (size_t)z * sC;

    const int tid = threadIdx.x;
    const int m0 = blockIdx.y * 128, n0 = blockIdx.x * 128;
    const int lr = tid >> 1;
    const int lc = (tid & 1) * 4;
    const float* Ag = A + (size_t)(m0 + lr) * K + lc;
    const float* Bg = B + (size_t)(n0 + lr) * K + lc;
    const int tx = tid & 15, ty = tid >> 4;

    float acc[8][8];
#pragma unroll
    for (int i = 0; i < 8; i++)
#pragma unroll
        for (int j = 0; j < 8; j++) acc[i][j] = 0.f;

    for (int k0 = 0; k0 < K; k0 += 8) {
        float4 a = *(const float4*)(Ag + k0);
        float4 b = *(const float4*)(Bg + k0);
        __syncthreads();
        As[lc + 0][lr] = a.x; As[lc + 1][lr] = a.y; As[lc + 2][lr] = a.z; As[lc + 3][lr] = a.w;
        Bs[lc + 0][lr] = b.x; Bs[lc + 1][lr] = b.y; Bs[lc + 2][lr] = b.z; Bs[lc + 3][lr] = b.w;
        __syncthreads();
#pragma unroll
        for (int kk = 0; kk < 8; kk++) {
            float av[8], bv[8];
            *(float4*)(av)     = *(const float4*)&As[kk][ty * 8];
            *(float4*)(av + 4) = *(const float4*)&As[kk][ty * 8 + 4];
            *(float4*)(bv)     = *(const float4*)&Bs[kk][tx * 8];
            *(float4*)(bv + 4) = *(const float4*)&Bs[kk][tx * 8 + 4];
#pragma unroll
            for (int i = 0; i < 8; i++)
#pragma unroll
                for (int j = 0; j < 8; j++) acc[i][j] = fmaf(av[i], bv[j], acc[i][j]);
        }
    }

    float bv0[8];
#pragma unroll
    for (int j = 0; j < 8; j++) bv0[j] = bias ? bias[n0 + tx * 8 + j] : 0.f;

#pragma unroll
    for (int i = 0; i < 8; i++) {
        size_t off = (size_t)(m0 + ty * 8 + i) * N + n0 + tx * 8;
        float4 o0, o1;
        o0.x = alpha * acc[i][0] + bv0[0]; o0.y = alpha * acc[i][1] + bv0[1];
        o0.z = alpha * acc[i][2] + bv0[2]; o0.w = alpha * acc[i][3] + bv0[3];
        o1.x = alpha * acc[i][4] + bv0[4]; o1.y = alpha * acc[i][5] + bv0[5];
        o1.z = alpha * acc[i][6] + bv0[6]; o1.w = alpha * acc[i][7] + bv0[7];
        *(float4*)(C + off)     = o0;
        *(float4*)(C + off + 4) = o1;
    }
}

// ---------------- NN SGEMM + elementwise add: C = A*B + E (batched) ----------
__global__ __launch_bounds__(256) void sgemm_nn_addE(
    const float* __restrict__ A, const float* __restrict__ B,
    const float* __restrict__ E, float* __restrict__ C,
    int M, int N, int K,
    size_t sA, size_t sB, size_t sE, size_t sC)
{
    __shared__ __align__(16) float As[8][128];
    __shared__ __align__(16) float Bs[8][128];

    const int z = blockIdx.z;
    A += (size_t)z * sA; B += (size_t)z * sB; E += (size_t)z * sE; C += (size_t)z * sC;

    const int tid = threadIdx.x;
    const int m0 = blockIdx.y * 128, n0 = blockIdx.x * 128;
    const int lr = tid >> 1;
    const int lc = (tid & 1) * 4;
    const float* Ag = A + (size_t)(m0 + lr) * K + lc;
    const int lrB = tid >> 5;
    const int lcB = (tid & 31) * 4;
    const int tx = tid & 15, ty = tid >> 4;

    float acc[8][8];
#pragma unroll
    for (int i = 0; i < 8; i++)
#pragma unroll
        for (int j = 0; j < 8; j++) acc[i][j] = 0.f;

    for (int k0 = 0; k0 < K; k0 += 8) {
        float4 a = *(const float4*)(Ag + k0);
        float4 b = *(const float4*)(B + (size_t)(k0 + lrB) * N + n0 + lcB);
        __syncthreads();
        As[lc + 0][lr] = a.x; As[lc + 1][lr] = a.y; As[lc + 2][lr] = a.z; As[lc + 3][lr] = a.w;
        *(float4*)&Bs[lrB][lcB] = b;
        __syncthreads();
#pragma unroll
        for (int kk = 0; kk < 8; kk++) {
            float av[8], bv[8];
            *(float4*)(av)     = *(const float4*)&As[kk][ty * 8];
            *(float4*)(av + 4) = *(const float4*)&As[kk][ty * 8 + 4];
            *(float4*)(bv)     = *(const float4*)&Bs[kk][tx * 8];
            *(float4*)(bv + 4) = *(const float4*)&Bs[kk][tx * 8 + 4];
#pragma unroll
            for (int i = 0; i < 8; i++)
#pragma unroll
                for (int j = 0; j < 8; j++) acc[i][j] = fmaf(av[i], bv[j], acc[i][j]);
        }
    }

#pragma unroll
    for (int i = 0; i < 8; i++) {
        size_t off = (size_t)(m0 + ty * 8 + i) * N + n0 + tx * 8;
        float4 e0 = *(const float4*)(E + off);
        float4 e1 = *(const float4*)(E + off + 4);
        float4 o0, o1;
        o0.x = acc[i][0] + e0.x; o0.y = acc[i][1] + e0.y;
        o0.z = acc[i][2] + e0.z; o0.w = acc[i][3] + e0.w;
        o1.x = acc[i][4] + e1.x; o1.y = acc[i][5] + e1.y;
        o1.z = acc[i][6] + e1.z; o1.w = acc[i][7] + e1.w;
        *(float4*)(C + off)     = o0;
        *(float4*)(C + off + 4) = o1;
    }
}

// ---------------- persistent LSTM v2 ----------------
// 128 blocks = 4 bg (32 batch rows) x 32 us (16 units -> 64 gate rows).
// ws (128 KB) + hs (64 KB) dynamic smem. c lives in registers. Barrier per bg.
#define WS_FLOATS (HDIM * 64)
#define HS_FLOATS (HDIM * 32)
__global__ __launch_bounds__(256, 1) void lstm_persistent2(const float* __restrict__ W_hh)
{
    extern __shared__ float sm[];
    float* ws = sm;                 // [k][64] : index iu*4 + gate
    float* hs = sm + WS_FLOATS;     // [k][32 local b]

    const int tid = threadIdx.x;
    const int bg = blockIdx.x >> 5;
    const int us = blockIdx.x & 31;
    const int iu = tid & 15;
    const int bq = tid >> 4;              // 0..15
    const int u  = us * 16 + iu;          // global unit
    const int bl = bq * 2;                // local batch pair base
    const int b0 = bg * 32 + bl;          // global batch row

    // one-time: stage W_hh slice into smem. r = iu*4+g covers the 64 gate rows.
    {
        const int r = tid >> 2;           // 0..63
        const int iu_r = r >> 2, g_r = r & 3;
        const size_t grow = ((size_t)(g_r * HDIM + us * 16 + iu_r)) * HDIM;
        for (int k = (tid & 3) * 4; k < HDIM; k += 16) {
            float4 w = *(const float4*)(W_hh + grow + k);
            ws[(k + 0) * 64 + r] = w.x;
            ws[(k + 1) * 64 + r] = w.y;
            ws[(k + 2) * 64 + r] = w.z;
            ws[(k + 3) * 64 + r] = w.w;
        }
    }

    // one-time: zero our slice of h0 (union over us covers all units of bg)
    for (int idx = tid; idx < 16 * 32; idx += 256)
        g_h2[bg * (HDIM * 32) + (us * 16 + (idx >> 5)) * 32 + (idx & 31)] = 0.f;

    float c0v = 0.f, c1v = 0.f;

    __syncthreads();
    bar_bg(bg, tid);

    for (int t = 0; t < SDEC; t++) {
        const int cur = t & 1, nxt = cur ^ 1;

        // prefetch x-part of gates (consumed at epilogue; latency hidden by GEMM)
        const size_t xbase = (size_t)t * G4H;
        float2 xg0 = *(const float2*)&g_xWt[(xbase + 0 * HDIM + u) * B_ + b0];
        float2 xg1 = *(const float2*)&g_xWt[(xbase + 1 * HDIM + u) * B_ + b0];
        float2 xg2 = *(const float2*)&g_xWt[(xbase + 2 * HDIM + u) * B_ + b0];
        float2 xg3 = *(const float2*)&g_xWt[(xbase + 3 * HDIM + u) * B_ + b0];

        // bulk-load this bg's h slice [512][32] into smem (L2-only: skip stale L1)
        const float* hsrc = g_h2 + cur * (4 * HDIM * 32) + bg * (HDIM * 32);
        for (int i = tid * 4; i < HS_FLOATS; i += 1024) {
            float4 v = __ldcg((const float4*)(hsrc + i));
            *(float4*)&hs[i] = v;
        }
        __syncthreads();

        // pure-smem GEMM: 4 gates x 2 batch via f32x2 (gate-pairs packed)
        unsigned long long a01a = 0, a23a = 0, a01b = 0, a23b = 0;
        const float* wp = ws + iu * 4;
        const float* hp = hs + bl;
#pragma unroll 16
        for (int k = 0; k < HDIM; k++) {
            ulonglong2 w2 = *(const ulonglong2*)(wp + k * 64);
            float2 hv = *(const float2*)(hp + k * 32);
            unsigned long long ha = dup2(hv.x);
            unsigned long long hb = dup2(hv.y);
            a01a = ffma2(w2.x, ha, a01a);
            a23a = ffma2(w2.y, ha, a23a);
            a01b = ffma2(w2.x, hb, a01b);
            a23b = ffma2(w2.y, hb, a23b);
        }

        // gates = h-part + x-part (biases folded into xW). lane0=gate(2j), lane1=gate(2j+1)
        float i0 = lo32(a01a) + xg0.x, f0 = hi32(a01a) + xg1.x;
        float gg0 = lo32(a23a) + xg2.x, o0 = hi32(a23a) + xg3.x;
        float i1 = lo32(a01b) + xg0.y, f1 = hi32(a01b) + xg1.y;
        float gg1 = lo32(a23b) + xg2.y, o1 = hi32(a23b) + xg3.y;

        c0v = sigmoidf_(f0) * c0v + sigmoidf_(i0) * tanhf(gg0);
        c1v = sigmoidf_(f1) * c1v + sigmoidf_(i1) * tanhf(gg1);
        float h0 = sigmoidf_(o0) * tanhf(c0v);
        float h1 = sigmoidf_(o1) * tanhf(c1v);

        *(float2*)&g_h2[nxt * (4 * HDIM * 32) + bg * (HDIM * 32) + u * 32 + bl] =
            make_float2(h0, h1);
        g_H[((size_t)b0 * SDEC + t) * HDIM + u]       = h0;
        g_H[((size_t)(b0 + 1) * SDEC + t) * HDIM + u] = h1;

        __syncthreads();     // everyone done reading hs + done writing h
        bar_bg(bg, tid);     // publish h_t to the other 31 blocks of this bg
    }
}

// ---------------- softmax over last dim (256) ----------------
__global__ __launch_bounds__(256) void softmax256(float* __restrict__ S) {
    __shared__ float red[256];
    const int t = threadIdx.x;
    float* p = S + (size_t)blockIdx.x * SENC;
    float v = p[t];
    red[t] = v; __syncthreads();
    for (int s = 128; s > 0; s >>= 1) { if (t < s) red[t] = fmaxf(red[t], red[t + s]); __syncthreads(); }
    float mx = red[0]; __syncthreads();
    float e = __expf(v - mx);
    red[t] = e; __syncthreads();
    for (int s = 128; s > 0; s >>= 1) { if (t < s) red[t] += red[t + s]; __syncthreads(); }
    p[t] = e * (1.0f / red[0]);
}

// ---------------- host ----------------
extern "C" void kernel_launch(void* const* d_in, const int* in_sizes, int n_in,
                              void* d_out, int out_size) {
    const float* x    = (const float*)d_in[0];
    const float* enc  = (const float*)d_in[1];
    const float* W_ih = (const float*)d_in[2];
    const float* W_hh = (const float*)d_in[3];
    const float* b_ih = (const float*)d_in[4];
    const float* b_hh = (const float*)d_in[5];
    const float* Wq   = (const float*)d_in[6];
    const float* bq   = (const float*)d_in[7];
    const float* Wk   = (const float*)d_in[8];
    const float* bk   = (const float*)d_in[9];
    const float* Wv   = (const float*)d_in[10];
    const float* bv   = (const float*)d_in[11];
    const float* Wfc  = (const float*)d_in[12];
    const float* bfc  = (const float*)d_in[13];
    float* out = (float*)d_out;

    float *p_xW, *p_K, *p_V, *p_H, *p_Q, *p_HC, *p_S, *p_bsum;
    cudaGetSymbolAddress((void**)&p_xW,  g_xW);
    cudaGetSymbolAddress((void**)&p_K,   g_K);
    cudaGetSymbolAddress((void**)&p_V,   g_V);
    cudaGetSymbolAddress((void**)&p_H,   g_H);
    cudaGetSymbolAddress((void**)&p_Q,   g_Q);
    cudaGetSymbolAddress((void**)&p_HC,  g_HC);
    cudaGetSymbolAddress((void**)&p_S,   g_S);
    cudaGetSymbolAddress((void**)&p_bsum,g_bsum);

    const float scale = 1.0f / sqrtf((float)HDIM);

    cudaFuncSetAttribute(lstm_persistent2,
                         cudaFuncAttributeMaxDynamicSharedMemorySize,
                         (WS_FLOATS + HS_FLOATS) * sizeof(float));

    bias_sum_kernel<<<G4H / 256, 256>>>(b_ih, b_hh);

    // xW = x @ W_ih^T + (b_ih + b_hh)      [32768 x 2048], K=256
    sgemm_nt<<<dim3(G4H / 128, MROWS / 128, 1), 256>>>(
        x, W_ih, p_bsum, p_xW, MROWS, G4H, IDIM, 1.0f, 0, 0, 0);
    // permute to [t][col][b] for the recurrence's coalesced per-step reads
    xw_transpose<<<dim3(G4H / 32, SDEC), 256>>>();
    // K = enc @ Wk^T + bk
    sgemm_nt<<<dim3(HDIM / 128, MROWS / 128, 1), 256>>>(
        enc, Wk, bk, p_K, MROWS, HDIM, HDIM, 1.0f, 0, 0, 0);
    // V = K @ Wv^T + bv
    sgemm_nt<<<dim3(HDIM / 128, MROWS / 128, 1), 256>>>(
        p_K, Wv, bv, p_V, MROWS, HDIM, HDIM, 1.0f, 0, 0, 0);

    // entire sequential LSTM in one persistent launch
    lstm_persistent2<<<128, 256, (WS_FLOATS + HS_FLOATS) * sizeof(float)>>>(W_hh);

    // Q = H @ Wq^T + bq
    sgemm_nt<<<dim3(HDIM / 128, MROWS / 128, 1), 256>>>(
        p_H, Wq, bq, p_Q, MROWS, HDIM, HDIM, 1.0f, 0, 0, 0);

    // scores: per-batch S[t,s] = scale * Q[t,:]·K[s,:]
    sgemm_nt<<<dim3(SENC / 128, SDEC / 128, B_), 256>>>(
        p_Q, p_K, nullptr, p_S, SDEC, SENC, HDIM, scale,
        (size_t)SDEC * HDIM, (size_t)SENC * HDIM, (size_t)SDEC * SENC);

    softmax256<<<B_ * SDEC, 256>>>(p_S);

    // context + h: HC[t,h] = sum_s S[t,s] * V[s,h] + H[t,h]
    sgemm_nn_addE<<<dim3(HDIM / 128, SDEC / 128, B_), 256>>>(
        p_S, p_V, p_H, p_HC, SDEC, HDIM, SENC,
        (size_t)SDEC * SENC, (size_t)SENC * HDIM,
        (size_t)SDEC * HDIM, (size_t)SDEC * HDIM);

    // out = HC @ Wfc^T + bfc               [32768 x 256]
    sgemm_nt<<<dim3(ODIM / 128, MROWS / 128, 1), 256>>>(
        p_HC, Wfc, bfc, out, MROWS, ODIM, HDIM, 1.0f, 0, 0, 0);
}